// round 12
// baseline (speedup 1.0000x reference)
#include <cuda_runtime.h>

// Gaussian 3D covariance: cov = (R*diag(exp(ls))) @ R^T per point.
// N=4M, pure HBM streaming. Final kernel = empirically best of 10
// variants (R9): TPB=256 (N = 2^8 * 5^6, exactly divisible — NOT by
// 512, which broke R10), 1 pt/thread, default cache policy (beats all
// .cs / evict-hint variants: L2 write-back aggregation + cross-replay
// read hits), smem-staged coalesced float4 flush, no tail paths.
// Measured: 36.6us kernel, 69% DRAM active, ~7.0 TB/s logical (87% of
// spec counting L2-absorbed reads) — mixed-stream DRAM ceiling.

constexpr int TPB = 256;

__global__ __launch_bounds__(TPB) void cov_kernel(
    const float4* __restrict__ quat,   // [n] as float4 (w,x,y,z)
    const float*  __restrict__ ls,     // [n*3]
    float*        __restrict__ out)    // [n*9]
{
    __shared__ __align__(16) float sbuf[TPB * 9];

    const int i = blockIdx.x * TPB + threadIdx.x;

    const float4 q4 = quat[i];
    const float sx = __expf(ls[3 * i + 0]);
    const float sy = __expf(ls[3 * i + 1]);
    const float sz = __expf(ls[3 * i + 2]);

    const float d   = q4.x * q4.x + q4.y * q4.y + q4.z * q4.z + q4.w * q4.w;
    const float inv = rsqrtf(fmaxf(d, 1e-24f));
    const float qw = q4.x * inv;
    const float qx = q4.y * inv;
    const float qy = q4.z * inv;
    const float qz = q4.w * inv;

    const float r00 = 1.f - 2.f * (qy * qy + qz * qz);
    const float r01 = 2.f * (qx * qy - qz * qw);
    const float r02 = 2.f * (qx * qz + qy * qw);
    const float r10 = 2.f * (qx * qy + qz * qw);
    const float r11 = 1.f - 2.f * (qx * qx + qz * qz);
    const float r12 = 2.f * (qy * qz - qx * qw);
    const float r20 = 2.f * (qx * qz - qy * qw);
    const float r21 = 2.f * (qy * qz + qx * qw);
    const float r22 = 1.f - 2.f * (qx * qx + qy * qy);

    const float a0 = r00 * sx, a1 = r01 * sy, a2 = r02 * sz;
    const float b0 = r10 * sx, b1 = r11 * sy, b2 = r12 * sz;
    const float c0 = r20 * sx, c1 = r21 * sy, c2 = r22 * sz;

    float* p = &sbuf[threadIdx.x * 9];
    p[0] = a0 * r00 + a1 * r01 + a2 * r02;
    p[1] = a0 * r10 + a1 * r11 + a2 * r12;
    p[2] = a0 * r20 + a1 * r21 + a2 * r22;
    p[3] = b0 * r00 + b1 * r01 + b2 * r02;
    p[4] = b0 * r10 + b1 * r11 + b2 * r12;
    p[5] = b0 * r20 + b1 * r21 + b2 * r22;
    p[6] = c0 * r00 + c1 * r01 + c2 * r02;
    p[7] = c0 * r10 + c1 * r11 + c2 * r12;
    p[8] = c0 * r20 + c1 * r21 + c2 * r22;

    __syncthreads();

    // Coalesced full-block flush: 2304 floats = 576 float4s, default policy.
    float4*       o4 = reinterpret_cast<float4*>(out + (long long)blockIdx.x * (TPB * 9));
    const float4* s4 = reinterpret_cast<const float4*>(sbuf);
    #pragma unroll
    for (int j = threadIdx.x; j < TPB * 9 / 4; j += TPB)
        o4[j] = s4[j];
}

extern "C" void kernel_launch(void* const* d_in, const int* in_sizes, int n_in,
                              void* d_out, int out_size) {
    const float4* quat = (const float4*)d_in[0];  // [N,4] float32
    const float*  ls   = (const float*)d_in[1];   // [N,3] float32
    float*        out  = (float*)d_out;           // [N,3,3] float32

    const int n = in_sizes[0] / 4;                // 4,000,000 (divisible by 256)
    cov_kernel<<<n / TPB, TPB>>>(quat, ls, out);
}

// round 13
// speedup vs baseline: 1.0038x; 1.0038x over previous
#include <cuda_runtime.h>

// Gaussian 3D covariance: cov = (R*diag(exp(ls))) @ R^T per point.
// N=4M, pure HBM streaming. FINAL kernel — best of 12 rounds.
//
// Roofline summary: 256 MB irreducible traffic (112 read + 144 write);
// measured ~5.3-5.5 TB/s DRAM (~198 MB/replay; ~58 MB of reads hit L2
// across graph replays) = ~7 TB/s logical, ~87% of 8 TB/s spec. Ten
// structural variants (2pt/thread, TMA bulk store, L2 evict_last/first
// policies, .cs hints, persistent grid+prefetch, v8.f32 256-bit ops,
// TPB 128/512) all land within the ±1.3us run-to-run noise band
// (established by identical-source R9 vs R12) -> mixed-stream DRAM
// controller ceiling, not a software limit.
//
// Config: TPB=256 (N = 2^8*5^6 exactly divisible; 512 is NOT), 1 pt/
// thread, default cache policy (L2 write-back aggregation + cross-
// replay read hits beat every explicit hint), smem-staged coalesced
// float4 flush, zero predication/tails. regs=31, occ ~88%.

constexpr int TPB = 256;

__global__ __launch_bounds__(TPB) void cov_kernel(
    const float4* __restrict__ quat,   // [n] as float4 (w,x,y,z)
    const float*  __restrict__ ls,     // [n*3]
    float*        __restrict__ out)    // [n*9]
{
    __shared__ __align__(16) float sbuf[TPB * 9];

    const int i = blockIdx.x * TPB + threadIdx.x;

    const float4 q4 = quat[i];
    const float sx = __expf(ls[3 * i + 0]);
    const float sy = __expf(ls[3 * i + 1]);
    const float sz = __expf(ls[3 * i + 2]);

    const float d   = q4.x * q4.x + q4.y * q4.y + q4.z * q4.z + q4.w * q4.w;
    const float inv = rsqrtf(fmaxf(d, 1e-24f));
    const float qw = q4.x * inv;
    const float qx = q4.y * inv;
    const float qy = q4.z * inv;
    const float qz = q4.w * inv;

    const float r00 = 1.f - 2.f * (qy * qy + qz * qz);
    const float r01 = 2.f * (qx * qy - qz * qw);
    const float r02 = 2.f * (qx * qz + qy * qw);
    const float r10 = 2.f * (qx * qy + qz * qw);
    const float r11 = 1.f - 2.f * (qx * qx + qz * qz);
    const float r12 = 2.f * (qy * qz - qx * qw);
    const float r20 = 2.f * (qx * qz - qy * qw);
    const float r21 = 2.f * (qy * qz + qx * qw);
    const float r22 = 1.f - 2.f * (qx * qx + qy * qy);

    const float a0 = r00 * sx, a1 = r01 * sy, a2 = r02 * sz;
    const float b0 = r10 * sx, b1 = r11 * sy, b2 = r12 * sz;
    const float c0 = r20 * sx, c1 = r21 * sy, c2 = r22 * sz;

    float* p = &sbuf[threadIdx.x * 9];
    p[0] = a0 * r00 + a1 * r01 + a2 * r02;
    p[1] = a0 * r10 + a1 * r11 + a2 * r12;
    p[2] = a0 * r20 + a1 * r21 + a2 * r22;
    p[3] = b0 * r00 + b1 * r01 + b2 * r02;
    p[4] = b0 * r10 + b1 * r11 + b2 * r12;
    p[5] = b0 * r20 + b1 * r21 + b2 * r22;
    p[6] = c0 * r00 + c1 * r01 + c2 * r02;
    p[7] = c0 * r10 + c1 * r11 + c2 * r12;
    p[8] = c0 * r20 + c1 * r21 + c2 * r22;

    __syncthreads();

    // Coalesced full-block flush: 2304 floats = 576 float4s, default policy.
    float4*       o4 = reinterpret_cast<float4*>(out + (long long)blockIdx.x * (TPB * 9));
    const float4* s4 = reinterpret_cast<const float4*>(sbuf);
    #pragma unroll
    for (int j = threadIdx.x; j < TPB * 9 / 4; j += TPB)
        o4[j] = s4[j];
}

extern "C" void kernel_launch(void* const* d_in, const int* in_sizes, int n_in,
                              void* d_out, int out_size) {
    const float4* quat = (const float4*)d_in[0];  // [N,4] float32
    const float*  ls   = (const float*)d_in[1];   // [N,3] float32
    float*        out  = (float*)d_out;           // [N,3,3] float32

    const int n = in_sizes[0] / 4;                // 4,000,000 (divisible by 256)
    cov_kernel<<<n / TPB, TPB>>>(quat, ls, out);
}